// round 11
// baseline (speedup 1.0000x reference)
#include <cuda_runtime.h>
#include <cuda_bf16.h>
#include <math.h>
#include <stdint.h>

#define BB 2
#define LL 8192
#define CC 256
#define KW 17
#define HALFW 8
#define NLEV 4
#define CTX_CHUNKS 32

__device__ __forceinline__ uint32_t smem_to_u32(const void* p) {
    uint32_t a;
    asm("{ .reg .u64 t; cvta.to.shared.u64 t, %1; cvt.u32.u64 %0, t; }" : "=r"(a) : "l"(p));
    return a;
}

#define CP_ASYNC16(dst, src) \
    asm volatile("cp.async.cg.shared.global [%0], [%1], 16;" :: "r"(dst), "l"(src))
#define CP_COMMIT() asm volatile("cp.async.commit_group;" ::: "memory")
#define CP_WAIT0()  asm volatile("cp.async.wait_group 0;" ::: "memory")
#define STS128A(addr, r0, r1, r2, r3) \
    asm volatile("st.shared.v4.b32 [%0], {%1, %2, %3, %4};" \
                 :: "r"(addr), "r"(r0), "r"(r1), "r"(r2), "r"(r3) : "memory")

// ================= device scratch =================
__device__ float g_h[BB * LL * CC];
__device__ float g_qkv[BB * LL * 3 * CC];
__device__ float g_ov[BB * LL * CC];
__device__ float g_lev0[BB * LL * CC];
__device__ float g_lev1[BB * (LL / 2) * CC];
__device__ float g_lev2[BB * (LL / 4) * CC];
__device__ float g_lev3[BB * (LL / 8) * CC];
__device__ float g_width[BB * LL];
__device__ float g_logits[BB * LL];
__device__ float g_gattn[BB * LL];
__device__ float g_ctxpart[NLEV * BB * CTX_CHUNKS * CC];
__device__ float g_film[BB * 2 * CC];

// weights pre-split [hi | lo] along K
__device__ __nv_bfloat16 g_w2stem[CC * 2 * 512];
__device__ __nv_bfloat16 g_w2qkv[3 * CC * 2 * CC];
__device__ __nv_bfloat16 g_w2out[CC * 2 * CC];

__device__ __forceinline__ float sigmoidf_(float x) { return 1.0f / (1.0f + expf(-x)); }

// ================= all weight splits in ONE kernel =================
__global__ void split_all_kernel(const float* __restrict__ stem_w,
                                 const float* __restrict__ qkv_w,
                                 const float* __restrict__ out_w) {
    int idx = blockIdx.x * blockDim.x + threadIdx.x;
    const int NSTEM = CC * 512;
    const int NQKV = 3 * CC * CC;
    const int NOUT = CC * CC;
    if (idx < NSTEM) {
        int k = idx & 511;
        int o = idx >> 9;
        int i = k & 255, tap = (k < CC) ? 0 : 1;
        float v = stem_w[(size_t)o * 512 + i * 2 + tap];
        __nv_bfloat16 h = __float2bfloat16(v);
        __nv_bfloat16 l = __float2bfloat16(v - __bfloat162float(h));
        size_t base = (size_t)o * 1024;
        g_w2stem[base + k] = h; g_w2stem[base + 512 + k] = l;
    } else if (idx < NSTEM + NQKV) {
        int j = idx - NSTEM;
        int m = j / CC, k = j - m * CC;
        float v = qkv_w[j];
        __nv_bfloat16 h = __float2bfloat16(v);
        __nv_bfloat16 l = __float2bfloat16(v - __bfloat162float(h));
        size_t base = (size_t)m * 2 * CC;
        g_w2qkv[base + k] = h; g_w2qkv[base + CC + k] = l;
    } else if (idx < NSTEM + NQKV + NOUT) {
        int j = idx - NSTEM - NQKV;
        int m = j / CC, k = j - m * CC;
        float v = out_w[j];
        __nv_bfloat16 h = __float2bfloat16(v);
        __nv_bfloat16 l = __float2bfloat16(v - __bfloat162float(h));
        size_t base = (size_t)m * 2 * CC;
        g_w2out[base + k] = h; g_w2out[base + CC + k] = l;
    }
}

// ================= fused-split HMMA GEMM, templated BM, occ-2 ==============
// C[M,N] = A[M,K](fp32) * Bw[N,2K](bf16 [hi|lo])^T (+bias), Ah*Bh+Ah*Bl+Al*Bh.
// stem!=0: logical A row m = [x[m-1,:] (0 if t==0) | x[m,:]].
// pool: optional fused mean-pool-by-2 output.
// wwp/wbp/wout: optional fused width head: wout[m] = sigmoid(A[m,:]·wwp + wbp[0])*8+0.5
#define BK 32
#define SP 40

template <int BM>
__device__ __forceinline__ void load_a_chunk(const float* __restrict__ A, int stem,
                                             int row, int K, int cbase, float4* av) {
    constexpr int NF4 = BM / 32;
    if (!stem) {
        const float* p = A + (size_t)row * K + cbase;
#pragma unroll
        for (int j = 0; j < NF4; j++) av[j] = *reinterpret_cast<const float4*>(p + 4 * j);
    } else {
        int t = row & (LL - 1);
#pragma unroll
        for (int j = 0; j < NF4; j++) {
            int col = cbase + 4 * j;
            if (col < CC) {
                av[j] = (t > 0) ? *reinterpret_cast<const float4*>(A + (size_t)(row - 1) * CC + col)
                                : make_float4(0.f, 0.f, 0.f, 0.f);
            } else {
                av[j] = *reinterpret_cast<const float4*>(A + (size_t)row * CC + col - CC);
            }
        }
    }
}

template <int BM>
__global__ void __launch_bounds__(256, 2) gemm_tpl(const float* __restrict__ A,
                                                   const __nv_bfloat16* __restrict__ Bw,
                                                   const float* __restrict__ bias,
                                                   float* __restrict__ C,
                                                   float* __restrict__ pool,
                                                   const float* __restrict__ wwp,
                                                   const float* __restrict__ wbp,
                                                   float* __restrict__ wout,
                                                   int M, int N, int K, int stem) {
    constexpr int ATILE = BM * SP;
    constexpr int BTILE = 128 * SP;
    constexpr int NF4 = BM / 32;
    constexpr int TPR = 256 / BM;
    constexpr int MT = BM / 32;

    extern __shared__ __align__(16) __nv_bfloat16 sm[];
    __nv_bfloat16* pAh = sm;
    __nv_bfloat16* pAl = sm + 2 * ATILE;
    __nv_bfloat16* pBh = sm + 4 * ATILE;
    __nv_bfloat16* pBl = sm + 4 * ATILE + 2 * BTILE;

    const int tid = threadIdx.x;
    const int lane = tid & 31;
    const int wid = tid >> 5;
    const int wm = (wid >> 2) * (BM / 2);
    const int wn = (wid & 3) * 32;
    const int m0 = blockIdx.y * BM;
    const int n0 = blockIdx.x * 128;

    float acc[MT][4][4];
#pragma unroll
    for (int i = 0; i < MT; i++)
#pragma unroll
        for (int j = 0; j < 4; j++)
#pragma unroll
            for (int r = 0; r < 4; r++) acc[i][j][r] = 0.0f;

    const int lrowA = tid / TPR;
    const int lcolA = (tid % TPR) * (32 / TPR);
    const int lrowB = tid >> 1;
    const int lhalfB = (tid & 1) * 16;
    const __nv_bfloat16* BgpH = Bw + (size_t)(n0 + lrowB) * (2 * K) + lhalfB;
    const __nv_bfloat16* BgpL = BgpH + K;

    const uint32_t uAh = smem_to_u32(pAh);
    const uint32_t uAl = smem_to_u32(pAl);
    const uint32_t uBh = smem_to_u32(pBh);
    const uint32_t uBl = smem_to_u32(pBl);

    const uint32_t aoffA = (uint32_t)(lrowA * SP + lcolA) * 2;
    const uint32_t boffB = (uint32_t)(lrowB * SP + lhalfB) * 2;

    float4 av[NF4];
    float ws = 0.0f;   // fused width accumulator

#define ACC_W(CB) do {                                                                  \
        if (wout) {                                                                     \
            _Pragma("unroll")                                                           \
            for (int j = 0; j < NF4; j++) {                                             \
                float4 w4 = *reinterpret_cast<const float4*>(wwp + (CB) + 4 * j);       \
                ws = fmaf(av[j].x, w4.x, ws); ws = fmaf(av[j].y, w4.y, ws);             \
                ws = fmaf(av[j].z, w4.z, ws); ws = fmaf(av[j].w, w4.w, ws);             \
            }                                                                           \
        }                                                                               \
    } while (0)

#define CONVERT_STS(BUF) do {                                                           \
        uint32_t hb[2 * NF4], lb[2 * NF4];                                              \
        _Pragma("unroll")                                                               \
        for (int j = 0; j < NF4; j++) {                                                 \
            __nv_bfloat162 h01 = __float22bfloat162_rn(make_float2(av[j].x, av[j].y));  \
            __nv_bfloat162 h23 = __float22bfloat162_rn(make_float2(av[j].z, av[j].w));  \
            float2 f01 = __bfloat1622float2(h01);                                       \
            float2 f23 = __bfloat1622float2(h23);                                       \
            __nv_bfloat162 l01 = __float22bfloat162_rn(make_float2(av[j].x - f01.x, av[j].y - f01.y)); \
            __nv_bfloat162 l23 = __float22bfloat162_rn(make_float2(av[j].z - f23.x, av[j].w - f23.y)); \
            hb[2 * j] = *reinterpret_cast<uint32_t*>(&h01);                             \
            hb[2 * j + 1] = *reinterpret_cast<uint32_t*>(&h23);                         \
            lb[2 * j] = *reinterpret_cast<uint32_t*>(&l01);                             \
            lb[2 * j + 1] = *reinterpret_cast<uint32_t*>(&l23);                         \
        }                                                                               \
        _Pragma("unroll")                                                               \
        for (int j = 0; j < NF4 / 2; j++) {                                             \
            STS128A(uAh + (BUF) * (ATILE * 2) + aoffA + j * 16,                         \
                    hb[4 * j], hb[4 * j + 1], hb[4 * j + 2], hb[4 * j + 3]);            \
            STS128A(uAl + (BUF) * (ATILE * 2) + aoffA + j * 16,                         \
                    lb[4 * j], lb[4 * j + 1], lb[4 * j + 2], lb[4 * j + 3]);            \
        }                                                                               \
    } while (0)

#define CP_B(BUF, KO) do {                                                              \
        uint32_t dh = uBh + (BUF) * (BTILE * 2) + boffB;                                \
        uint32_t dl = uBl + (BUF) * (BTILE * 2) + boffB;                                \
        CP_ASYNC16(dh,      BgpH + (KO));                                               \
        CP_ASYNC16(dh + 16, BgpH + (KO) + 8);                                           \
        CP_ASYNC16(dl,      BgpL + (KO));                                               \
        CP_ASYNC16(dl + 16, BgpL + (KO) + 8);                                           \
    } while (0)

    const int NT = K / BK;

    CP_B(0, 0);
    CP_COMMIT();
    load_a_chunk<BM>(A, stem, m0 + lrowA, K, lcolA, av);
    ACC_W(lcolA);
    CONVERT_STS(0);
    if (NT > 1) {
        load_a_chunk<BM>(A, stem, m0 + lrowA, K, BK + lcolA, av);
        ACC_W(BK + lcolA);
    }
    CP_WAIT0();
    __syncthreads();

    for (int it = 0; it < NT; it++) {
        const int buf = it & 1;
        const bool more = (it + 1) < NT;
        if (more) {
            CP_B(buf ^ 1, (it + 1) * BK);
            CP_COMMIT();
            CONVERT_STS(buf ^ 1);
            if (it + 2 < NT) {
                load_a_chunk<BM>(A, stem, m0 + lrowA, K, (it + 2) * BK + lcolA, av);
                ACC_W((it + 2) * BK + lcolA);
            }
        }
#pragma unroll
        for (int ks = 0; ks < 2; ks++) {
            uint32_t bhf[4][2], blf[4][2];
            const int quad = lane >> 3;
            const int brr = lane & 7;
#pragma unroll
            for (int p = 0; p < 2; p++) {
                int row = wn + (p * 2 + (quad >> 1)) * 8 + brr;
                int col = ks * 16 + (quad & 1) * 8;
                uint32_t addr = uBh + buf * (BTILE * 2) + (uint32_t)(row * SP + col) * 2;
                asm("ldmatrix.sync.aligned.m8n8.x4.shared.b16 {%0,%1,%2,%3}, [%4];"
                    : "=r"(bhf[p * 2][0]), "=r"(bhf[p * 2][1]),
                      "=r"(bhf[p * 2 + 1][0]), "=r"(bhf[p * 2 + 1][1])
                    : "r"(addr));
                uint32_t addr2 = uBl + buf * (BTILE * 2) + (uint32_t)(row * SP + col) * 2;
                asm("ldmatrix.sync.aligned.m8n8.x4.shared.b16 {%0,%1,%2,%3}, [%4];"
                    : "=r"(blf[p * 2][0]), "=r"(blf[p * 2][1]),
                      "=r"(blf[p * 2 + 1][0]), "=r"(blf[p * 2 + 1][1])
                    : "r"(addr2));
            }
            const int arow = lane & 15;
            const int acol = ks * 16 + ((lane >> 4) << 3);
#define DO_MMA(AC, AF, BF)                                                      \
            asm("mma.sync.aligned.m16n8k16.row.col.f32.bf16.bf16.f32 "           \
                "{%0,%1,%2,%3}, {%4,%5,%6,%7}, {%8,%9}, {%0,%1,%2,%3};"          \
                : "+f"((AC)[0]), "+f"((AC)[1]), "+f"((AC)[2]), "+f"((AC)[3])     \
                : "r"((AF)[0]), "r"((AF)[1]), "r"((AF)[2]), "r"((AF)[3]),        \
                  "r"((BF)[0]), "r"((BF)[1]))
#pragma unroll
            for (int mt = 0; mt < MT; mt++) {
                uint32_t ah[4], al[4];
                uint32_t addr = uAh + buf * (ATILE * 2) +
                                (uint32_t)((wm + mt * 16 + arow) * SP + acol) * 2;
                asm("ldmatrix.sync.aligned.m8n8.x4.shared.b16 {%0,%1,%2,%3}, [%4];"
                    : "=r"(ah[0]), "=r"(ah[1]), "=r"(ah[2]), "=r"(ah[3])
                    : "r"(addr));
                uint32_t addr2 = uAl + buf * (ATILE * 2) +
                                 (uint32_t)((wm + mt * 16 + arow) * SP + acol) * 2;
                asm("ldmatrix.sync.aligned.m8n8.x4.shared.b16 {%0,%1,%2,%3}, [%4];"
                    : "=r"(al[0]), "=r"(al[1]), "=r"(al[2]), "=r"(al[3])
                    : "r"(addr2));
#pragma unroll
                for (int nt = 0; nt < 4; nt++) DO_MMA(acc[mt][nt], ah, bhf[nt]);
#pragma unroll
                for (int nt = 0; nt < 4; nt++) DO_MMA(acc[mt][nt], ah, blf[nt]);
#pragma unroll
                for (int nt = 0; nt < 4; nt++) DO_MMA(acc[mt][nt], al, bhf[nt]);
            }
#undef DO_MMA
        }
        if (more) {
            CP_WAIT0();
            __syncthreads();
        }
    }
#undef CONVERT_STS
#undef CP_B
#undef ACC_W

    // fused width write (same value from every N-tile CTA; bitwise identical)
    if (wout) {
#pragma unroll
        for (int o = 1; o < TPR; o <<= 1) ws += __shfl_xor_sync(0xffffffffu, ws, o);
        if ((tid & (TPR - 1)) == 0)
            wout[m0 + lrowA] = sigmoidf_(ws + wbp[0]) * (float)HALFW + 0.5f;
    }

    // epilogue (+ optional fused mean-pool by 2)
    const int g = lane >> 2;
    const int t = lane & 3;
#pragma unroll
    for (int mt = 0; mt < MT; mt++) {
#pragma unroll
        for (int nt = 0; nt < 4; nt++) {
            int row = m0 + wm + mt * 16 + g;
            int col = n0 + wn + nt * 8 + 2 * t;
            float b0 = 0.f, b1 = 0.f;
            if (bias) { b0 = bias[col]; b1 = bias[col + 1]; }
            float2 v0, v1;
            v0.x = acc[mt][nt][0] + b0; v0.y = acc[mt][nt][1] + b1;
            v1.x = acc[mt][nt][2] + b0; v1.y = acc[mt][nt][3] + b1;
            *reinterpret_cast<float2*>(C + (size_t)row * N + col) = v0;
            *reinterpret_cast<float2*>(C + (size_t)(row + 8) * N + col) = v1;
            if (pool) {
                float p00 = v0.x + __shfl_xor_sync(0xffffffffu, v0.x, 4);
                float p01 = v0.y + __shfl_xor_sync(0xffffffffu, v0.y, 4);
                float p10 = v1.x + __shfl_xor_sync(0xffffffffu, v1.x, 4);
                float p11 = v1.y + __shfl_xor_sync(0xffffffffu, v1.y, 4);
                if ((g & 1) == 0) {
                    float2 q0, q1;
                    q0.x = 0.5f * p00; q0.y = 0.5f * p01;
                    q1.x = 0.5f * p10; q1.y = 0.5f * p11;
                    *reinterpret_cast<float2*>(pool + (size_t)(row >> 1) * N + col) = q0;
                    *reinterpret_cast<float2*>(pool + (size_t)((row + 8) >> 1) * N + col) = q1;
                }
            }
        }
    }
}

// ================= windowed attention: 2 pos/warp, 32 pos/block, 512 thr ====
__global__ void __launch_bounds__(512) attn_kernel(const float* __restrict__ qkv,
                                                   const float* __restrict__ width,
                                                   float* __restrict__ ov,
                                                   int l) {
    extern __shared__ float smem_attn[];
    float* sk = smem_attn;              // [48][256]
    float* sv = smem_attn + 48 * 256;   // [48][256]

    const int tid = threadIdx.x;
    const int lane = tid & 31;
    const int wid = tid >> 5;           // 0..15
    const int nb = l >> 5;
    const int b = blockIdx.x / nb;
    const int t0 = (blockIdx.x - b * nb) << 5;

    // rows t0-8 .. t0+39 (zero-pad OOB)
    for (int idx = tid; idx < 48 * 64; idx += 512) {
        int row = idx >> 6;
        int c4 = (idx & 63) << 2;
        int kt = t0 - HALFW + row;
        float4 kv = make_float4(0.f, 0.f, 0.f, 0.f);
        float4 vv = kv;
        if (kt >= 0 && kt < l) {
            const float* base = qkv + ((size_t)(b * l + kt)) * (3 * CC);
            kv = *reinterpret_cast<const float4*>(base + CC + c4);
            vv = *reinterpret_cast<const float4*>(base + 2 * CC + c4);
        }
        *reinterpret_cast<float4*>(sk + row * 256 + c4) = kv;
        *reinterpret_cast<float4*>(sv + row * 256 + c4) = vv;
    }
    __syncthreads();

    // warp handles positions p0 = t0+2*wid, p1 = p0+1; window rows 2*wid + [0,18)
    const int p0 = t0 + 2 * wid;
    const float* q0r = qkv + (size_t)(b * l + p0) * (3 * CC);
    const float* q1r = q0r + 3 * CC;

    float q0[8], q1[8];
#pragma unroll
    for (int j = 0; j < 8; j++) {
        int c = lane + 32 * j;
        q0[j] = q0r[c];
        q1[j] = q1r[c];
    }
    float width0 = width[(size_t)b * l + p0];
    float width1 = width[(size_t)b * l + p0 + 1];

    float s0[KW], s1[KW];
#pragma unroll
    for (int r = 0; r < 18; r++) {
        const float* krow = sk + (2 * wid + r) * 256;
        float kv[8];
#pragma unroll
        for (int j = 0; j < 8; j++) kv[j] = krow[lane + 32 * j];
        if (r < KW) {
            float p = 0.0f;
#pragma unroll
            for (int j = 0; j < 8; j++) p = fmaf(q0[j], kv[j], p);
            s0[r] = p;
        }
        if (r > 0) {
            float p = 0.0f;
#pragma unroll
            for (int j = 0; j < 8; j++) p = fmaf(q1[j], kv[j], p);
            s1[r - 1] = p;
        }
    }
#pragma unroll
    for (int w = 0; w < KW; w++) {
        float a = s0[w], c = s1[w];
#pragma unroll
        for (int o = 16; o > 0; o >>= 1) {
            a += __shfl_xor_sync(0xffffffffu, a, o);
            c += __shfl_xor_sync(0xffffffffu, c, o);
        }
        float rel = fabsf((float)(w - HALFW));
        s0[w] = a * 0.0625f - (1.0f - sigmoidf_((width0 - rel) * 5.0f)) * 10000.0f;
        s1[w] = c * 0.0625f - (1.0f - sigmoidf_((width1 - rel) * 5.0f)) * 10000.0f;
    }

    float mx0 = s0[0], mx1 = s1[0];
#pragma unroll
    for (int w = 1; w < KW; w++) { mx0 = fmaxf(mx0, s0[w]); mx1 = fmaxf(mx1, s1[w]); }
    float d0 = 0.0f, d1 = 0.0f;
#pragma unroll
    for (int w = 0; w < KW; w++) {
        s0[w] = expf(s0[w] - mx0); d0 += s0[w];
        s1[w] = expf(s1[w] - mx1); d1 += s1[w];
    }
    float i0 = 1.0f / d0, i1 = 1.0f / d1;
#pragma unroll
    for (int w = 0; w < KW; w++) { s0[w] *= i0; s1[w] *= i1; }

    float o0[8], o1[8];
    const float* vs0 = sv + (2 * wid + HALFW) * 256;
#pragma unroll
    for (int j = 0; j < 8; j++) {
        o0[j] = vs0[lane + 32 * j];
        o1[j] = vs0[256 + lane + 32 * j];
    }
#pragma unroll
    for (int r = 0; r < 18; r++) {
        const float* vrow = sv + (2 * wid + r) * 256;
        float vv[8];
#pragma unroll
        for (int j = 0; j < 8; j++) vv[j] = vrow[lane + 32 * j];
        if (r < KW) {
            float a = s0[r];
#pragma unroll
            for (int j = 0; j < 8; j++) o0[j] = fmaf(a, vv[j], o0[j]);
        }
        if (r > 0) {
            float a = s1[r - 1];
#pragma unroll
            for (int j = 0; j < 8; j++) o1[j] = fmaf(a, vv[j], o1[j]);
        }
    }
    float* or0 = ov + (size_t)(b * l + p0) * CC;
#pragma unroll
    for (int j = 0; j < 8; j++) {
        or0[lane + 32 * j] = o0[j];
        or0[CC + lane + 32 * j] = o1[j];
    }
}

// ================= global attention logits (float4) =================
__global__ void logits_kernel(const float* __restrict__ query) {
    int gwarp = (blockIdx.x * blockDim.x + threadIdx.x) >> 5;
    int lane = threadIdx.x & 31;
    if (gwarp >= BB * LL) return;
    int b = gwarp / LL;
    int t = gwarp - b * LL;
    const float* r0 = g_lev0 + ((size_t)(b * LL + t)) * CC;
    const float* r1 = g_lev1 + ((size_t)(b * (LL / 2) + (t >> 1))) * CC;
    const float* r2 = g_lev2 + ((size_t)(b * (LL / 4) + (t >> 2))) * CC;
    const float* r3 = g_lev3 + ((size_t)(b * (LL / 8) + (t >> 3))) * CC;
    float s = 0.0f;
#pragma unroll
    for (int j = 0; j < 2; j++) {
        int c = (lane + 32 * j) * 4;
        float4 a0 = *reinterpret_cast<const float4*>(r0 + c);
        float4 a1 = *reinterpret_cast<const float4*>(r1 + c);
        float4 a2 = *reinterpret_cast<const float4*>(r2 + c);
        float4 a3 = *reinterpret_cast<const float4*>(r3 + c);
        float4 q0 = *reinterpret_cast<const float4*>(query + c);
        float4 q1 = *reinterpret_cast<const float4*>(query + CC + c);
        float4 q2 = *reinterpret_cast<const float4*>(query + 2 * CC + c);
        float4 q3 = *reinterpret_cast<const float4*>(query + 3 * CC + c);
        s = fmaf(a0.x, q0.x, s); s = fmaf(a0.y, q0.y, s); s = fmaf(a0.z, q0.z, s); s = fmaf(a0.w, q0.w, s);
        s = fmaf(a1.x, q1.x, s); s = fmaf(a1.y, q1.y, s); s = fmaf(a1.z, q1.z, s); s = fmaf(a1.w, q1.w, s);
        s = fmaf(a2.x, q2.x, s); s = fmaf(a2.y, q2.y, s); s = fmaf(a2.z, q2.z, s); s = fmaf(a2.w, q2.w, s);
        s = fmaf(a3.x, q3.x, s); s = fmaf(a3.y, q3.y, s); s = fmaf(a3.z, q3.z, s); s = fmaf(a3.w, q3.w, s);
    }
#pragma unroll
    for (int o = 16; o > 0; o >>= 1) s += __shfl_xor_sync(0xffffffffu, s, o);
    if (lane == 0) g_logits[gwarp] = s;
}

// ================= softmax over L per batch (1024 thr) =================
__global__ void softmax_kernel() {
    __shared__ float sl[LL];
    __shared__ float red[1024];
    int b = blockIdx.x;
    int tid = threadIdx.x;
    const float* lg = g_logits + (size_t)b * LL;
    float mx = -1e30f;
    for (int t = tid; t < LL; t += 1024) { float v = lg[t]; sl[t] = v; mx = fmaxf(mx, v); }
    red[tid] = mx; __syncthreads();
    for (int o = 512; o > 0; o >>= 1) { if (tid < o) red[tid] = fmaxf(red[tid], red[tid + o]); __syncthreads(); }
    mx = red[0]; __syncthreads();
    float sum = 0.0f;
    for (int t = tid; t < LL; t += 1024) { float e = expf(sl[t] - mx); sl[t] = e; sum += e; }
    red[tid] = sum; __syncthreads();
    for (int o = 512; o > 0; o >>= 1) { if (tid < o) red[tid] += red[tid + o]; __syncthreads(); }
    float inv = 1.0f / red[0];
    for (int t = tid; t < LL; t += 1024) g_gattn[(size_t)b * LL + t] = sl[t] * inv;
}

// ================= ctx partial reduction =================
__global__ void ctx_part_kernel() {
    int i = blockIdx.x;
    int b = blockIdx.y;
    int ch = blockIdx.z;
    int c = threadIdx.x;
    const float* lev = (i == 0) ? g_lev0 : (i == 1) ? g_lev1 : (i == 2) ? g_lev2 : g_lev3;
    int li = LL >> i;
    const float* ga = g_gattn + (size_t)b * LL;
    const float* base = lev + (size_t)b * li * CC + c;
    const int span = LL / CTX_CHUNKS;
    const int t0 = ch * span;
    float a0 = 0.f, a1 = 0.f, a2 = 0.f, a3 = 0.f;
    for (int t = t0; t < t0 + span; t += 4) {
        a0 = fmaf(ga[t + 0], base[(size_t)((t + 0) >> i) * CC], a0);
        a1 = fmaf(ga[t + 1], base[(size_t)((t + 1) >> i) * CC], a1);
        a2 = fmaf(ga[t + 2], base[(size_t)((t + 2) >> i) * CC], a2);
        a3 = fmaf(ga[t + 3], base[(size_t)((t + 3) >> i) * CC], a3);
    }
    g_ctxpart[(((size_t)i * BB + b) * CTX_CHUNKS + ch) * CC + c] = (a0 + a1) + (a2 + a3);
}

// ================= FiLM (folds ctx reduction) =================
__global__ void film_kernel(const float* __restrict__ film_w, const float* __restrict__ film_b) {
    __shared__ float sc[NLEV * CC];
    int b = blockIdx.x;
    int o = threadIdx.x;
    for (int d = o; d < NLEV * CC; d += 512) {
        int i = d >> 8, c = d & 255;
        const float* p = g_ctxpart + (((size_t)i * BB + b) * CTX_CHUNKS) * CC + c;
        float s = 0.0f;
#pragma unroll
        for (int ch = 0; ch < CTX_CHUNKS; ch++) s += p[(size_t)ch * CC];
        sc[d] = s;
    }
    __syncthreads();
    const float* wr = film_w + (size_t)o * (NLEV * CC);
    float acc = 0.0f;
#pragma unroll 8
    for (int d = 0; d < NLEV * CC; d++) acc = fmaf(sc[d], wr[d], acc);
    g_film[(size_t)b * (2 * CC) + o] = acc + film_b[o];
}

// ================= final (float4) =================
__global__ void final_kernel(float* __restrict__ out) {
    int idx = blockIdx.x * blockDim.x + threadIdx.x;
    if (idx >= BB * LL * CC / 4) return;
    int c4 = (idx << 2) & (CC - 1);
    int b = (idx << 2) / (LL * CC);
    float4 lv = *reinterpret_cast<const float4*>(&g_lev0[(size_t)idx << 2]);
    const float* fb = g_film + (size_t)b * (2 * CC);
    float4 sc = *reinterpret_cast<const float4*>(fb + c4);
    float4 bi = *reinterpret_cast<const float4*>(fb + CC + c4);
    float4 r;
    r.x = fmaf(lv.x, 1.0f + sc.x, bi.x);
    r.y = fmaf(lv.y, 1.0f + sc.y, bi.y);
    r.z = fmaf(lv.z, 1.0f + sc.z, bi.z);
    r.w = fmaf(lv.w, 1.0f + sc.w, bi.w);
    *reinterpret_cast<float4*>(out + ((size_t)idx << 2)) = r;
}

// ================= launch =================
static void launch_gemm(const float* A, const __nv_bfloat16* Bw, const float* bias,
                        float* C, float* pool,
                        const float* wwp, const float* wbp, float* wout,
                        int M, int N, int K, int stem) {
    int ctas128 = (N / 128) * (M / 128);
    if (ctas128 >= 148) {
        int smem = (4 * 128 + 4 * 128) * SP * 2;
        cudaFuncSetAttribute(gemm_tpl<128>, cudaFuncAttributeMaxDynamicSharedMemorySize, smem);
        dim3 grid(N / 128, M / 128);
        gemm_tpl<128><<<grid, 256, smem>>>(A, Bw, bias, C, pool, wwp, wbp, wout, M, N, K, stem);
    } else {
        int smem = (4 * 64 + 4 * 128) * SP * 2;
        cudaFuncSetAttribute(gemm_tpl<64>, cudaFuncAttributeMaxDynamicSharedMemorySize, smem);
        dim3 grid(N / 128, M / 64);
        gemm_tpl<64><<<grid, 256, smem>>>(A, Bw, bias, C, pool, wwp, wbp, wout, M, N, K, stem);
    }
}

extern "C" void kernel_launch(void* const* d_in, const int* in_sizes, int n_in,
                              void* d_out, int out_size) {
    const float* x       = (const float*)d_in[0];
    const float* stem_w  = (const float*)d_in[1];
    const float* stem_b  = (const float*)d_in[2];
    const float* qkv_w   = (const float*)d_in[3];
    const float* width_w = (const float*)d_in[4];
    const float* width_b = (const float*)d_in[5];
    const float* out_w   = (const float*)d_in[6];
    const float* query   = (const float*)d_in[7];
    const float* film_w  = (const float*)d_in[8];
    const float* film_b  = (const float*)d_in[9];
    float* out = (float*)d_out;

    cudaFuncSetAttribute(attn_kernel, cudaFuncAttributeMaxDynamicSharedMemorySize, 98304);

    float *p_h, *p_qkv, *p_ov, *p_width, *p_lev[4];
    __nv_bfloat16 *p_w2stem, *p_w2qkv, *p_w2out;
    cudaGetSymbolAddress((void**)&p_h, g_h);
    cudaGetSymbolAddress((void**)&p_qkv, g_qkv);
    cudaGetSymbolAddress((void**)&p_ov, g_ov);
    cudaGetSymbolAddress((void**)&p_width, g_width);
    cudaGetSymbolAddress((void**)&p_lev[0], g_lev0);
    cudaGetSymbolAddress((void**)&p_lev[1], g_lev1);
    cudaGetSymbolAddress((void**)&p_lev[2], g_lev2);
    cudaGetSymbolAddress((void**)&p_lev[3], g_lev3);
    cudaGetSymbolAddress((void**)&p_w2stem, g_w2stem);
    cudaGetSymbolAddress((void**)&p_w2qkv, g_w2qkv);
    cudaGetSymbolAddress((void**)&p_w2out, g_w2out);

    const int M = BB * LL;

    {
        int total = CC * 512 + 3 * CC * CC + CC * CC;
        split_all_kernel<<<(total + 255) / 256, 256>>>(stem_w, qkv_w, out_w);
    }

    // stem
    launch_gemm(x, p_w2stem, stem_b, p_h, nullptr, nullptr, nullptr, nullptr, M, CC, 512, 1);

    // levels (width fused into QKV GEMM; downsample fused into out-proj)
    for (int i = 0; i < NLEV; i++) {
        int l = LL >> i;
        int Mi = BB * l;
        launch_gemm(p_h, p_w2qkv, nullptr, p_qkv, nullptr,
                    width_w, width_b, p_width, Mi, 3 * CC, CC, 0);
        attn_kernel<<<Mi / 32, 512, 98304>>>(p_qkv, p_width, p_ov, l);
        float* pool = (i < NLEV - 1) ? p_h : nullptr;
        launch_gemm(p_ov, p_w2out, nullptr, p_lev[i], pool,
                    nullptr, nullptr, nullptr, Mi, CC, CC, 0);
    }

    // global attention + FiLM
    logits_kernel<<<(BB * LL) / 8, 256>>>(query);
    softmax_kernel<<<BB, 1024>>>();
    ctx_part_kernel<<<dim3(NLEV, BB, CTX_CHUNKS), CC>>>();
    film_kernel<<<BB, 2 * CC>>>(film_w, film_b);
    final_kernel<<<(BB * LL * CC / 4 + 255) / 256, 256>>>(out);
}

// round 12
// speedup vs baseline: 1.0048x; 1.0048x over previous
#include <cuda_runtime.h>
#include <cuda_bf16.h>
#include <math.h>
#include <stdint.h>

#define BB 2
#define LL 8192
#define CC 256
#define KW 17
#define HALFW 8
#define NLEV 4
#define CTX_CHUNKS 32

__device__ __forceinline__ uint32_t smem_to_u32(const void* p) {
    uint32_t a;
    asm("{ .reg .u64 t; cvta.to.shared.u64 t, %1; cvt.u32.u64 %0, t; }" : "=r"(a) : "l"(p));
    return a;
}

#define CP_ASYNC16(dst, src) \
    asm volatile("cp.async.cg.shared.global [%0], [%1], 16;" :: "r"(dst), "l"(src))
#define CP_COMMIT() asm volatile("cp.async.commit_group;" ::: "memory")
#define CP_WAIT0()  asm volatile("cp.async.wait_group 0;" ::: "memory")
#define STS128A(addr, r0, r1, r2, r3) \
    asm volatile("st.shared.v4.b32 [%0], {%1, %2, %3, %4};" \
                 :: "r"(addr), "r"(r0), "r"(r1), "r"(r2), "r"(r3) : "memory")

// ================= device scratch =================
__device__ float g_h[BB * LL * CC];
__device__ float g_qkv[BB * LL * 3 * CC];
__device__ float g_ov[BB * LL * CC];
__device__ float g_lev0[BB * LL * CC];
__device__ float g_lev1[BB * (LL / 2) * CC];
__device__ float g_lev2[BB * (LL / 4) * CC];
__device__ float g_lev3[BB * (LL / 8) * CC];
__device__ float g_width[BB * LL];
__device__ float g_logits[BB * LL];
__device__ float g_gattn[BB * LL];
__device__ float g_ctxpart[NLEV * BB * CTX_CHUNKS * CC];
__device__ float g_film[BB * 2 * CC];

// weights pre-split [hi | lo] along K
__device__ __nv_bfloat16 g_w2stem[CC * 2 * 512];
__device__ __nv_bfloat16 g_w2qkv[3 * CC * 2 * CC];
__device__ __nv_bfloat16 g_w2out[CC * 2 * CC];

__device__ __forceinline__ float sigmoidf_(float x) { return 1.0f / (1.0f + expf(-x)); }

// ================= all weight splits in ONE kernel =================
__global__ void split_all_kernel(const float* __restrict__ stem_w,
                                 const float* __restrict__ qkv_w,
                                 const float* __restrict__ out_w) {
    int idx = blockIdx.x * blockDim.x + threadIdx.x;
    const int NSTEM = CC * 512;
    const int NQKV = 3 * CC * CC;
    const int NOUT = CC * CC;
    if (idx < NSTEM) {
        int k = idx & 511;
        int o = idx >> 9;
        int i = k & 255, tap = (k < CC) ? 0 : 1;
        float v = stem_w[(size_t)o * 512 + i * 2 + tap];
        __nv_bfloat16 h = __float2bfloat16(v);
        __nv_bfloat16 l = __float2bfloat16(v - __bfloat162float(h));
        size_t base = (size_t)o * 1024;
        g_w2stem[base + k] = h; g_w2stem[base + 512 + k] = l;
    } else if (idx < NSTEM + NQKV) {
        int j = idx - NSTEM;
        int m = j / CC, k = j - m * CC;
        float v = qkv_w[j];
        __nv_bfloat16 h = __float2bfloat16(v);
        __nv_bfloat16 l = __float2bfloat16(v - __bfloat162float(h));
        size_t base = (size_t)m * 2 * CC;
        g_w2qkv[base + k] = h; g_w2qkv[base + CC + k] = l;
    } else if (idx < NSTEM + NQKV + NOUT) {
        int j = idx - NSTEM - NQKV;
        int m = j / CC, k = j - m * CC;
        float v = out_w[j];
        __nv_bfloat16 h = __float2bfloat16(v);
        __nv_bfloat16 l = __float2bfloat16(v - __bfloat162float(h));
        size_t base = (size_t)m * 2 * CC;
        g_w2out[base + k] = h; g_w2out[base + CC + k] = l;
    }
}

// ================= fused-split HMMA GEMM, templated BM, occ-2 ==============
// C[M,N] = A[M,K](fp32) * Bw[N,2K](bf16 [hi|lo])^T (+bias), Ah*Bh+Ah*Bl+Al*Bh.
// stem!=0: logical A row m = [x[m-1,:] (0 if t==0) | x[m,:]].
// pool: optional fused mean-pool-by-2 output.
// wwp/wbp/wout: optional fused width head: wout[m] = sigmoid(A[m,:]·wwp + wbp[0])*8+0.5
#define BK 32
#define SP 40

template <int BM>
__device__ __forceinline__ void load_a_chunk(const float* __restrict__ A, int stem,
                                             int row, int K, int cbase, float4* av) {
    constexpr int NF4 = BM / 32;
    if (!stem) {
        const float* p = A + (size_t)row * K + cbase;
#pragma unroll
        for (int j = 0; j < NF4; j++) av[j] = *reinterpret_cast<const float4*>(p + 4 * j);
    } else {
        int t = row & (LL - 1);
#pragma unroll
        for (int j = 0; j < NF4; j++) {
            int col = cbase + 4 * j;
            if (col < CC) {
                av[j] = (t > 0) ? *reinterpret_cast<const float4*>(A + (size_t)(row - 1) * CC + col)
                                : make_float4(0.f, 0.f, 0.f, 0.f);
            } else {
                av[j] = *reinterpret_cast<const float4*>(A + (size_t)row * CC + col - CC);
            }
        }
    }
}

template <int BM>
__global__ void __launch_bounds__(256, 2) gemm_tpl(const float* __restrict__ A,
                                                   const __nv_bfloat16* __restrict__ Bw,
                                                   const float* __restrict__ bias,
                                                   float* __restrict__ C,
                                                   float* __restrict__ pool,
                                                   const float* __restrict__ wwp,
                                                   const float* __restrict__ wbp,
                                                   float* __restrict__ wout,
                                                   int M, int N, int K, int stem) {
    constexpr int ATILE = BM * SP;
    constexpr int BTILE = 128 * SP;
    constexpr int NF4 = BM / 32;
    constexpr int TPR = 256 / BM;
    constexpr int MT = BM / 32;

    extern __shared__ __align__(16) __nv_bfloat16 sm[];
    __nv_bfloat16* pAh = sm;
    __nv_bfloat16* pAl = sm + 2 * ATILE;
    __nv_bfloat16* pBh = sm + 4 * ATILE;
    __nv_bfloat16* pBl = sm + 4 * ATILE + 2 * BTILE;

    const int tid = threadIdx.x;
    const int lane = tid & 31;
    const int wid = tid >> 5;
    const int wm = (wid >> 2) * (BM / 2);
    const int wn = (wid & 3) * 32;
    const int m0 = blockIdx.y * BM;
    const int n0 = blockIdx.x * 128;

    float acc[MT][4][4];
#pragma unroll
    for (int i = 0; i < MT; i++)
#pragma unroll
        for (int j = 0; j < 4; j++)
#pragma unroll
            for (int r = 0; r < 4; r++) acc[i][j][r] = 0.0f;

    const int lrowA = tid / TPR;
    const int lcolA = (tid % TPR) * (32 / TPR);
    const int lrowB = tid >> 1;
    const int lhalfB = (tid & 1) * 16;
    const __nv_bfloat16* BgpH = Bw + (size_t)(n0 + lrowB) * (2 * K) + lhalfB;
    const __nv_bfloat16* BgpL = BgpH + K;

    const uint32_t uAh = smem_to_u32(pAh);
    const uint32_t uAl = smem_to_u32(pAl);
    const uint32_t uBh = smem_to_u32(pBh);
    const uint32_t uBl = smem_to_u32(pBl);

    const uint32_t aoffA = (uint32_t)(lrowA * SP + lcolA) * 2;
    const uint32_t boffB = (uint32_t)(lrowB * SP + lhalfB) * 2;

    float4 av[NF4];
    float ws = 0.0f;   // fused width accumulator

#define ACC_W(CB) do {                                                                  \
        if (wout) {                                                                     \
            _Pragma("unroll")                                                           \
            for (int j = 0; j < NF4; j++) {                                             \
                float4 w4 = *reinterpret_cast<const float4*>(wwp + (CB) + 4 * j);       \
                ws = fmaf(av[j].x, w4.x, ws); ws = fmaf(av[j].y, w4.y, ws);             \
                ws = fmaf(av[j].z, w4.z, ws); ws = fmaf(av[j].w, w4.w, ws);             \
            }                                                                           \
        }                                                                               \
    } while (0)

#define CONVERT_STS(BUF) do {                                                           \
        uint32_t hb[2 * NF4], lb[2 * NF4];                                              \
        _Pragma("unroll")                                                               \
        for (int j = 0; j < NF4; j++) {                                                 \
            __nv_bfloat162 h01 = __float22bfloat162_rn(make_float2(av[j].x, av[j].y));  \
            __nv_bfloat162 h23 = __float22bfloat162_rn(make_float2(av[j].z, av[j].w));  \
            float2 f01 = __bfloat1622float2(h01);                                       \
            float2 f23 = __bfloat1622float2(h23);                                       \
            __nv_bfloat162 l01 = __float22bfloat162_rn(make_float2(av[j].x - f01.x, av[j].y - f01.y)); \
            __nv_bfloat162 l23 = __float22bfloat162_rn(make_float2(av[j].z - f23.x, av[j].w - f23.y)); \
            hb[2 * j] = *reinterpret_cast<uint32_t*>(&h01);                             \
            hb[2 * j + 1] = *reinterpret_cast<uint32_t*>(&h23);                         \
            lb[2 * j] = *reinterpret_cast<uint32_t*>(&l01);                             \
            lb[2 * j + 1] = *reinterpret_cast<uint32_t*>(&l23);                         \
        }                                                                               \
        _Pragma("unroll")                                                               \
        for (int j = 0; j < NF4 / 2; j++) {                                             \
            STS128A(uAh + (BUF) * (ATILE * 2) + aoffA + j * 16,                         \
                    hb[4 * j], hb[4 * j + 1], hb[4 * j + 2], hb[4 * j + 3]);            \
            STS128A(uAl + (BUF) * (ATILE * 2) + aoffA + j * 16,                         \
                    lb[4 * j], lb[4 * j + 1], lb[4 * j + 2], lb[4 * j + 3]);            \
        }                                                                               \
    } while (0)

#define CP_B(BUF, KO) do {                                                              \
        uint32_t dh = uBh + (BUF) * (BTILE * 2) + boffB;                                \
        uint32_t dl = uBl + (BUF) * (BTILE * 2) + boffB;                                \
        CP_ASYNC16(dh,      BgpH + (KO));                                               \
        CP_ASYNC16(dh + 16, BgpH + (KO) + 8);                                           \
        CP_ASYNC16(dl,      BgpL + (KO));                                               \
        CP_ASYNC16(dl + 16, BgpL + (KO) + 8);                                           \
    } while (0)

    const int NT = K / BK;

    CP_B(0, 0);
    CP_COMMIT();
    load_a_chunk<BM>(A, stem, m0 + lrowA, K, lcolA, av);
    ACC_W(lcolA);
    CONVERT_STS(0);
    if (NT > 1) {
        load_a_chunk<BM>(A, stem, m0 + lrowA, K, BK + lcolA, av);
        ACC_W(BK + lcolA);
    }
    CP_WAIT0();
    __syncthreads();

    for (int it = 0; it < NT; it++) {
        const int buf = it & 1;
        const bool more = (it + 1) < NT;
        if (more) {
            CP_B(buf ^ 1, (it + 1) * BK);
            CP_COMMIT();
            CONVERT_STS(buf ^ 1);
            if (it + 2 < NT) {
                load_a_chunk<BM>(A, stem, m0 + lrowA, K, (it + 2) * BK + lcolA, av);
                ACC_W((it + 2) * BK + lcolA);
            }
        }
#pragma unroll
        for (int ks = 0; ks < 2; ks++) {
            uint32_t bhf[4][2], blf[4][2];
            const int quad = lane >> 3;
            const int brr = lane & 7;
#pragma unroll
            for (int p = 0; p < 2; p++) {
                int row = wn + (p * 2 + (quad >> 1)) * 8 + brr;
                int col = ks * 16 + (quad & 1) * 8;
                uint32_t addr = uBh + buf * (BTILE * 2) + (uint32_t)(row * SP + col) * 2;
                asm("ldmatrix.sync.aligned.m8n8.x4.shared.b16 {%0,%1,%2,%3}, [%4];"
                    : "=r"(bhf[p * 2][0]), "=r"(bhf[p * 2][1]),
                      "=r"(bhf[p * 2 + 1][0]), "=r"(bhf[p * 2 + 1][1])
                    : "r"(addr));
                uint32_t addr2 = uBl + buf * (BTILE * 2) + (uint32_t)(row * SP + col) * 2;
                asm("ldmatrix.sync.aligned.m8n8.x4.shared.b16 {%0,%1,%2,%3}, [%4];"
                    : "=r"(blf[p * 2][0]), "=r"(blf[p * 2][1]),
                      "=r"(blf[p * 2 + 1][0]), "=r"(blf[p * 2 + 1][1])
                    : "r"(addr2));
            }
            const int arow = lane & 15;
            const int acol = ks * 16 + ((lane >> 4) << 3);
#define DO_MMA(AC, AF, BF)                                                      \
            asm("mma.sync.aligned.m16n8k16.row.col.f32.bf16.bf16.f32 "           \
                "{%0,%1,%2,%3}, {%4,%5,%6,%7}, {%8,%9}, {%0,%1,%2,%3};"          \
                : "+f"((AC)[0]), "+f"((AC)[1]), "+f"((AC)[2]), "+f"((AC)[3])     \
                : "r"((AF)[0]), "r"((AF)[1]), "r"((AF)[2]), "r"((AF)[3]),        \
                  "r"((BF)[0]), "r"((BF)[1]))
#pragma unroll
            for (int mt = 0; mt < MT; mt++) {
                uint32_t ah[4], al[4];
                uint32_t addr = uAh + buf * (ATILE * 2) +
                                (uint32_t)((wm + mt * 16 + arow) * SP + acol) * 2;
                asm("ldmatrix.sync.aligned.m8n8.x4.shared.b16 {%0,%1,%2,%3}, [%4];"
                    : "=r"(ah[0]), "=r"(ah[1]), "=r"(ah[2]), "=r"(ah[3])
                    : "r"(addr));
                uint32_t addr2 = uAl + buf * (ATILE * 2) +
                                 (uint32_t)((wm + mt * 16 + arow) * SP + acol) * 2;
                asm("ldmatrix.sync.aligned.m8n8.x4.shared.b16 {%0,%1,%2,%3}, [%4];"
                    : "=r"(al[0]), "=r"(al[1]), "=r"(al[2]), "=r"(al[3])
                    : "r"(addr2));
#pragma unroll
                for (int nt = 0; nt < 4; nt++) DO_MMA(acc[mt][nt], ah, bhf[nt]);
#pragma unroll
                for (int nt = 0; nt < 4; nt++) DO_MMA(acc[mt][nt], ah, blf[nt]);
#pragma unroll
                for (int nt = 0; nt < 4; nt++) DO_MMA(acc[mt][nt], al, bhf[nt]);
            }
#undef DO_MMA
        }
        if (more) {
            CP_WAIT0();
            __syncthreads();
        }
    }
#undef CONVERT_STS
#undef CP_B
#undef ACC_W

    // fused width write (same value from every N-tile CTA; bitwise identical)
    if (wout) {
#pragma unroll
        for (int o = 1; o < TPR; o <<= 1) ws += __shfl_xor_sync(0xffffffffu, ws, o);
        if ((tid & (TPR - 1)) == 0)
            wout[m0 + lrowA] = sigmoidf_(ws + wbp[0]) * (float)HALFW + 0.5f;
    }

    // epilogue (+ optional fused mean-pool by 2)
    const int g = lane >> 2;
    const int t = lane & 3;
#pragma unroll
    for (int mt = 0; mt < MT; mt++) {
#pragma unroll
        for (int nt = 0; nt < 4; nt++) {
            int row = m0 + wm + mt * 16 + g;
            int col = n0 + wn + nt * 8 + 2 * t;
            float b0 = 0.f, b1 = 0.f;
            if (bias) { b0 = bias[col]; b1 = bias[col + 1]; }
            float2 v0, v1;
            v0.x = acc[mt][nt][0] + b0; v0.y = acc[mt][nt][1] + b1;
            v1.x = acc[mt][nt][2] + b0; v1.y = acc[mt][nt][3] + b1;
            *reinterpret_cast<float2*>(C + (size_t)row * N + col) = v0;
            *reinterpret_cast<float2*>(C + (size_t)(row + 8) * N + col) = v1;
            if (pool) {
                float p00 = v0.x + __shfl_xor_sync(0xffffffffu, v0.x, 4);
                float p01 = v0.y + __shfl_xor_sync(0xffffffffu, v0.y, 4);
                float p10 = v1.x + __shfl_xor_sync(0xffffffffu, v1.x, 4);
                float p11 = v1.y + __shfl_xor_sync(0xffffffffu, v1.y, 4);
                if ((g & 1) == 0) {
                    float2 q0, q1;
                    q0.x = 0.5f * p00; q0.y = 0.5f * p01;
                    q1.x = 0.5f * p10; q1.y = 0.5f * p11;
                    *reinterpret_cast<float2*>(pool + (size_t)(row >> 1) * N + col) = q0;
                    *reinterpret_cast<float2*>(pool + (size_t)((row + 8) >> 1) * N + col) = q1;
                }
            }
        }
    }
}

// ================= windowed attention: 2 pos/warp, 16 pos/block, 256 thr ====
// (R10 geometry — validated 2 CTAs/SM — with precomputed width)
__global__ void __launch_bounds__(256, 2) attn_kernel(const float* __restrict__ qkv,
                                                      const float* __restrict__ width,
                                                      float* __restrict__ ov,
                                                      int l) {
    extern __shared__ float smem_attn[];
    float* sk = smem_attn;              // [32][256]
    float* sv = smem_attn + 32 * 256;   // [32][256]

    const int tid = threadIdx.x;
    const int lane = tid & 31;
    const int wid = tid >> 5;           // 0..7
    const int nb = l >> 4;
    const int b = blockIdx.x / nb;
    const int t0 = (blockIdx.x - b * nb) << 4;

    // rows t0-8 .. t0+23 (zero-pad OOB)
    for (int idx = tid; idx < 32 * 64; idx += 256) {
        int row = idx >> 6;
        int c4 = (idx & 63) << 2;
        int kt = t0 - HALFW + row;
        float4 kv = make_float4(0.f, 0.f, 0.f, 0.f);
        float4 vv = kv;
        if (kt >= 0 && kt < l) {
            const float* base = qkv + ((size_t)(b * l + kt)) * (3 * CC);
            kv = *reinterpret_cast<const float4*>(base + CC + c4);
            vv = *reinterpret_cast<const float4*>(base + 2 * CC + c4);
        }
        *reinterpret_cast<float4*>(sk + row * 256 + c4) = kv;
        *reinterpret_cast<float4*>(sv + row * 256 + c4) = vv;
    }
    __syncthreads();

    // warp handles positions p0 = t0+2*wid, p1 = p0+1; window rows 2*wid + [0,18)
    const int p0 = t0 + 2 * wid;
    const float* q0r = qkv + (size_t)(b * l + p0) * (3 * CC);
    const float* q1r = q0r + 3 * CC;

    float q0[8], q1[8];
#pragma unroll
    for (int j = 0; j < 8; j++) {
        int c = lane + 32 * j;
        q0[j] = q0r[c];
        q1[j] = q1r[c];
    }
    float width0 = width[(size_t)b * l + p0];
    float width1 = width[(size_t)b * l + p0 + 1];

    float s0[KW], s1[KW];
#pragma unroll
    for (int r = 0; r < 18; r++) {
        const float* krow = sk + (2 * wid + r) * 256;
        float kv[8];
#pragma unroll
        for (int j = 0; j < 8; j++) kv[j] = krow[lane + 32 * j];
        if (r < KW) {
            float p = 0.0f;
#pragma unroll
            for (int j = 0; j < 8; j++) p = fmaf(q0[j], kv[j], p);
            s0[r] = p;
        }
        if (r > 0) {
            float p = 0.0f;
#pragma unroll
            for (int j = 0; j < 8; j++) p = fmaf(q1[j], kv[j], p);
            s1[r - 1] = p;
        }
    }
#pragma unroll
    for (int w = 0; w < KW; w++) {
        float a = s0[w], c = s1[w];
#pragma unroll
        for (int o = 16; o > 0; o >>= 1) {
            a += __shfl_xor_sync(0xffffffffu, a, o);
            c += __shfl_xor_sync(0xffffffffu, c, o);
        }
        float rel = fabsf((float)(w - HALFW));
        s0[w] = a * 0.0625f - (1.0f - sigmoidf_((width0 - rel) * 5.0f)) * 10000.0f;
        s1[w] = c * 0.0625f - (1.0f - sigmoidf_((width1 - rel) * 5.0f)) * 10000.0f;
    }

    float mx0 = s0[0], mx1 = s1[0];
#pragma unroll
    for (int w = 1; w < KW; w++) { mx0 = fmaxf(mx0, s0[w]); mx1 = fmaxf(mx1, s1[w]); }
    float d0 = 0.0f, d1 = 0.0f;
#pragma unroll
    for (int w = 0; w < KW; w++) {
        s0[w] = expf(s0[w] - mx0); d0 += s0[w];
        s1[w] = expf(s1[w] - mx1); d1 += s1[w];
    }
    float i0 = 1.0f / d0, i1 = 1.0f / d1;
#pragma unroll
    for (int w = 0; w < KW; w++) { s0[w] *= i0; s1[w] *= i1; }

    float o0[8], o1[8];
    const float* vs0 = sv + (2 * wid + HALFW) * 256;
#pragma unroll
    for (int j = 0; j < 8; j++) {
        o0[j] = vs0[lane + 32 * j];               // "+ v" for p0
        o1[j] = vs0[256 + lane + 32 * j];         // "+ v" for p1
    }
#pragma unroll
    for (int r = 0; r < 18; r++) {
        const float* vrow = sv + (2 * wid + r) * 256;
        float vv[8];
#pragma unroll
        for (int j = 0; j < 8; j++) vv[j] = vrow[lane + 32 * j];
        if (r < KW) {
            float a = s0[r];
#pragma unroll
            for (int j = 0; j < 8; j++) o0[j] = fmaf(a, vv[j], o0[j]);
        }
        if (r > 0) {
            float a = s1[r - 1];
#pragma unroll
            for (int j = 0; j < 8; j++) o1[j] = fmaf(a, vv[j], o1[j]);
        }
    }
    float* or0 = ov + (size_t)(b * l + p0) * CC;
#pragma unroll
    for (int j = 0; j < 8; j++) {
        or0[lane + 32 * j] = o0[j];
        or0[CC + lane + 32 * j] = o1[j];
    }
}

// ================= global attention logits (float4) =================
__global__ void logits_kernel(const float* __restrict__ query) {
    int gwarp = (blockIdx.x * blockDim.x + threadIdx.x) >> 5;
    int lane = threadIdx.x & 31;
    if (gwarp >= BB * LL) return;
    int b = gwarp / LL;
    int t = gwarp - b * LL;
    const float* r0 = g_lev0 + ((size_t)(b * LL + t)) * CC;
    const float* r1 = g_lev1 + ((size_t)(b * (LL / 2) + (t >> 1))) * CC;
    const float* r2 = g_lev2 + ((size_t)(b * (LL / 4) + (t >> 2))) * CC;
    const float* r3 = g_lev3 + ((size_t)(b * (LL / 8) + (t >> 3))) * CC;
    float s = 0.0f;
#pragma unroll
    for (int j = 0; j < 2; j++) {
        int c = (lane + 32 * j) * 4;
        float4 a0 = *reinterpret_cast<const float4*>(r0 + c);
        float4 a1 = *reinterpret_cast<const float4*>(r1 + c);
        float4 a2 = *reinterpret_cast<const float4*>(r2 + c);
        float4 a3 = *reinterpret_cast<const float4*>(r3 + c);
        float4 q0 = *reinterpret_cast<const float4*>(query + c);
        float4 q1 = *reinterpret_cast<const float4*>(query + CC + c);
        float4 q2 = *reinterpret_cast<const float4*>(query + 2 * CC + c);
        float4 q3 = *reinterpret_cast<const float4*>(query + 3 * CC + c);
        s = fmaf(a0.x, q0.x, s); s = fmaf(a0.y, q0.y, s); s = fmaf(a0.z, q0.z, s); s = fmaf(a0.w, q0.w, s);
        s = fmaf(a1.x, q1.x, s); s = fmaf(a1.y, q1.y, s); s = fmaf(a1.z, q1.z, s); s = fmaf(a1.w, q1.w, s);
        s = fmaf(a2.x, q2.x, s); s = fmaf(a2.y, q2.y, s); s = fmaf(a2.z, q2.z, s); s = fmaf(a2.w, q2.w, s);
        s = fmaf(a3.x, q3.x, s); s = fmaf(a3.y, q3.y, s); s = fmaf(a3.z, q3.z, s); s = fmaf(a3.w, q3.w, s);
    }
#pragma unroll
    for (int o = 16; o > 0; o >>= 1) s += __shfl_xor_sync(0xffffffffu, s, o);
    if (lane == 0) g_logits[gwarp] = s;
}

// ================= softmax over L per batch (1024 thr) =================
__global__ void softmax_kernel() {
    __shared__ float sl[LL];
    __shared__ float red[1024];
    int b = blockIdx.x;
    int tid = threadIdx.x;
    const float* lg = g_logits + (size_t)b * LL;
    float mx = -1e30f;
    for (int t = tid; t < LL; t += 1024) { float v = lg[t]; sl[t] = v; mx = fmaxf(mx, v); }
    red[tid] = mx; __syncthreads();
    for (int o = 512; o > 0; o >>= 1) { if (tid < o) red[tid] = fmaxf(red[tid], red[tid + o]); __syncthreads(); }
    mx = red[0]; __syncthreads();
    float sum = 0.0f;
    for (int t = tid; t < LL; t += 1024) { float e = expf(sl[t] - mx); sl[t] = e; sum += e; }
    red[tid] = sum; __syncthreads();
    for (int o = 512; o > 0; o >>= 1) { if (tid < o) red[tid] += red[tid + o]; __syncthreads(); }
    float inv = 1.0f / red[0];
    for (int t = tid; t < LL; t += 1024) g_gattn[(size_t)b * LL + t] = sl[t] * inv;
}

// ================= ctx partial reduction =================
__global__ void ctx_part_kernel() {
    int i = blockIdx.x;
    int b = blockIdx.y;
    int ch = blockIdx.z;
    int c = threadIdx.x;
    const float* lev = (i == 0) ? g_lev0 : (i == 1) ? g_lev1 : (i == 2) ? g_lev2 : g_lev3;
    int li = LL >> i;
    const float* ga = g_gattn + (size_t)b * LL;
    const float* base = lev + (size_t)b * li * CC + c;
    const int span = LL / CTX_CHUNKS;
    const int t0 = ch * span;
    float a0 = 0.f, a1 = 0.f, a2 = 0.f, a3 = 0.f;
    for (int t = t0; t < t0 + span; t += 4) {
        a0 = fmaf(ga[t + 0], base[(size_t)((t + 0) >> i) * CC], a0);
        a1 = fmaf(ga[t + 1], base[(size_t)((t + 1) >> i) * CC], a1);
        a2 = fmaf(ga[t + 2], base[(size_t)((t + 2) >> i) * CC], a2);
        a3 = fmaf(ga[t + 3], base[(size_t)((t + 3) >> i) * CC], a3);
    }
    g_ctxpart[(((size_t)i * BB + b) * CTX_CHUNKS + ch) * CC + c] = (a0 + a1) + (a2 + a3);
}

// ================= FiLM (folds ctx reduction) =================
__global__ void film_kernel(const float* __restrict__ film_w, const float* __restrict__ film_b) {
    __shared__ float sc[NLEV * CC];
    int b = blockIdx.x;
    int o = threadIdx.x;
    for (int d = o; d < NLEV * CC; d += 512) {
        int i = d >> 8, c = d & 255;
        const float* p = g_ctxpart + (((size_t)i * BB + b) * CTX_CHUNKS) * CC + c;
        float s = 0.0f;
#pragma unroll
        for (int ch = 0; ch < CTX_CHUNKS; ch++) s += p[(size_t)ch * CC];
        sc[d] = s;
    }
    __syncthreads();
    const float* wr = film_w + (size_t)o * (NLEV * CC);
    float acc = 0.0f;
#pragma unroll 8
    for (int d = 0; d < NLEV * CC; d++) acc = fmaf(sc[d], wr[d], acc);
    g_film[(size_t)b * (2 * CC) + o] = acc + film_b[o];
}

// ================= final (float4) =================
__global__ void final_kernel(float* __restrict__ out) {
    int idx = blockIdx.x * blockDim.x + threadIdx.x;
    if (idx >= BB * LL * CC / 4) return;
    int c4 = (idx << 2) & (CC - 1);
    int b = (idx << 2) / (LL * CC);
    float4 lv = *reinterpret_cast<const float4*>(&g_lev0[(size_t)idx << 2]);
    const float* fb = g_film + (size_t)b * (2 * CC);
    float4 sc = *reinterpret_cast<const float4*>(fb + c4);
    float4 bi = *reinterpret_cast<const float4*>(fb + CC + c4);
    float4 r;
    r.x = fmaf(lv.x, 1.0f + sc.x, bi.x);
    r.y = fmaf(lv.y, 1.0f + sc.y, bi.y);
    r.z = fmaf(lv.z, 1.0f + sc.z, bi.z);
    r.w = fmaf(lv.w, 1.0f + sc.w, bi.w);
    *reinterpret_cast<float4*>(out + ((size_t)idx << 2)) = r;
}

// ================= launch =================
static void launch_gemm(const float* A, const __nv_bfloat16* Bw, const float* bias,
                        float* C, float* pool,
                        const float* wwp, const float* wbp, float* wout,
                        int M, int N, int K, int stem) {
    int ctas128 = (N / 128) * (M / 128);
    if (ctas128 >= 148) {
        int smem = (4 * 128 + 4 * 128) * SP * 2;
        cudaFuncSetAttribute(gemm_tpl<128>, cudaFuncAttributeMaxDynamicSharedMemorySize, smem);
        dim3 grid(N / 128, M / 128);
        gemm_tpl<128><<<grid, 256, smem>>>(A, Bw, bias, C, pool, wwp, wbp, wout, M, N, K, stem);
    } else {
        int smem = (4 * 64 + 4 * 128) * SP * 2;
        cudaFuncSetAttribute(gemm_tpl<64>, cudaFuncAttributeMaxDynamicSharedMemorySize, smem);
        dim3 grid(N / 128, M / 64);
        gemm_tpl<64><<<grid, 256, smem>>>(A, Bw, bias, C, pool, wwp, wbp, wout, M, N, K, stem);
    }
}

extern "C" void kernel_launch(void* const* d_in, const int* in_sizes, int n_in,
                              void* d_out, int out_size) {
    const float* x       = (const float*)d_in[0];
    const float* stem_w  = (const float*)d_in[1];
    const float* stem_b  = (const float*)d_in[2];
    const float* qkv_w   = (const float*)d_in[3];
    const float* width_w = (const float*)d_in[4];
    const float* width_b = (const float*)d_in[5];
    const float* out_w   = (const float*)d_in[6];
    const float* query   = (const float*)d_in[7];
    const float* film_w  = (const float*)d_in[8];
    const float* film_b  = (const float*)d_in[9];
    float* out = (float*)d_out;

    cudaFuncSetAttribute(attn_kernel, cudaFuncAttributeMaxDynamicSharedMemorySize, 65536);

    float *p_h, *p_qkv, *p_ov, *p_width, *p_lev[4];
    __nv_bfloat16 *p_w2stem, *p_w2qkv, *p_w2out;
    cudaGetSymbolAddress((void**)&p_h, g_h);
    cudaGetSymbolAddress((void**)&p_qkv, g_qkv);
    cudaGetSymbolAddress((void**)&p_ov, g_ov);
    cudaGetSymbolAddress((void**)&p_width, g_width);
    cudaGetSymbolAddress((void**)&p_lev[0], g_lev0);
    cudaGetSymbolAddress((void**)&p_lev[1], g_lev1);
    cudaGetSymbolAddress((void**)&p_lev[2], g_lev2);
    cudaGetSymbolAddress((void**)&p_lev[3], g_lev3);
    cudaGetSymbolAddress((void**)&p_w2stem, g_w2stem);
    cudaGetSymbolAddress((void**)&p_w2qkv, g_w2qkv);
    cudaGetSymbolAddress((void**)&p_w2out, g_w2out);

    const int M = BB * LL;

    {
        int total = CC * 512 + 3 * CC * CC + CC * CC;
        split_all_kernel<<<(total + 255) / 256, 256>>>(stem_w, qkv_w, out_w);
    }

    // stem
    launch_gemm(x, p_w2stem, stem_b, p_h, nullptr, nullptr, nullptr, nullptr, M, CC, 512, 1);

    // levels (width fused into QKV GEMM; downsample fused into out-proj)
    for (int i = 0; i < NLEV; i++) {
        int l = LL >> i;
        int Mi = BB * l;
        launch_gemm(p_h, p_w2qkv, nullptr, p_qkv, nullptr,
                    width_w, width_b, p_width, Mi, 3 * CC, CC, 0);
        attn_kernel<<<Mi / 16, 256, 65536>>>(p_qkv, p_width, p_ov, l);
        float* pool = (i < NLEV - 1) ? p_h : nullptr;
        launch_gemm(p_ov, p_w2out, nullptr, p_lev[i], pool,
                    nullptr, nullptr, nullptr, Mi, CC, CC, 0);
    }

    // global attention + FiLM
    logits_kernel<<<(BB * LL) / 8, 256>>>(query);
    softmax_kernel<<<BB, 1024>>>();
    ctx_part_kernel<<<dim3(NLEV, BB, CTX_CHUNKS), CC>>>();
    film_kernel<<<BB, 2 * CC>>>(film_w, film_b);
    final_kernel<<<(BB * LL * CC / 4 + 255) / 256, 256>>>(out);
}

// round 13
// speedup vs baseline: 1.0525x; 1.0474x over previous
#include <cuda_runtime.h>
#include <cuda_bf16.h>
#include <math.h>
#include <stdint.h>

#define BB 2
#define LL 8192
#define CC 256
#define KW 17
#define HALFW 8
#define NLEV 4
#define CTX_CHUNKS 64

__device__ __forceinline__ uint32_t smem_to_u32(const void* p) {
    uint32_t a;
    asm("{ .reg .u64 t; cvta.to.shared.u64 t, %1; cvt.u32.u64 %0, t; }" : "=r"(a) : "l"(p));
    return a;
}

#define CP_ASYNC16(dst, src) \
    asm volatile("cp.async.cg.shared.global [%0], [%1], 16;" :: "r"(dst), "l"(src))
#define CP_COMMIT() asm volatile("cp.async.commit_group;" ::: "memory")
#define CP_WAIT0()  asm volatile("cp.async.wait_group 0;" ::: "memory")
#define STS128A(addr, r0, r1, r2, r3) \
    asm volatile("st.shared.v4.b32 [%0], {%1, %2, %3, %4};" \
                 :: "r"(addr), "r"(r0), "r"(r1), "r"(r2), "r"(r3) : "memory")

// ================= device scratch =================
__device__ float g_h[BB * LL * CC];
__device__ float g_qkv[BB * LL * 3 * CC];
__device__ float g_ov[BB * LL * CC];
__device__ float g_lev0[BB * LL * CC];
__device__ float g_lev1[BB * (LL / 2) * CC];
__device__ float g_lev2[BB * (LL / 4) * CC];
__device__ float g_lev3[BB * (LL / 8) * CC];
__device__ float g_logits[BB * LL];
__device__ float g_gattn[BB * LL];
__device__ float g_ctxpart[NLEV * BB * CTX_CHUNKS * CC];
__device__ float g_film[BB * 2 * CC];

// weights pre-split [hi | lo] along K
__device__ __nv_bfloat16 g_w2stem[CC * 2 * 512];
__device__ __nv_bfloat16 g_w2qkv[3 * CC * 2 * CC];
__device__ __nv_bfloat16 g_w2out[CC * 2 * CC];

__device__ __forceinline__ float sigmoidf_(float x) { return 1.0f / (1.0f + __expf(-x)); }

// ================= all weight splits in ONE kernel =================
__global__ void split_all_kernel(const float* __restrict__ stem_w,
                                 const float* __restrict__ qkv_w,
                                 const float* __restrict__ out_w) {
    int idx = blockIdx.x * blockDim.x + threadIdx.x;
    const int NSTEM = CC * 512;
    const int NQKV = 3 * CC * CC;
    const int NOUT = CC * CC;
    if (idx < NSTEM) {
        int k = idx & 511;
        int o = idx >> 9;
        int i = k & 255, tap = (k < CC) ? 0 : 1;
        float v = stem_w[(size_t)o * 512 + i * 2 + tap];
        __nv_bfloat16 h = __float2bfloat16(v);
        __nv_bfloat16 l = __float2bfloat16(v - __bfloat162float(h));
        size_t base = (size_t)o * 1024;
        g_w2stem[base + k] = h; g_w2stem[base + 512 + k] = l;
    } else if (idx < NSTEM + NQKV) {
        int j = idx - NSTEM;
        int m = j / CC, k = j - m * CC;
        float v = qkv_w[j];
        __nv_bfloat16 h = __float2bfloat16(v);
        __nv_bfloat16 l = __float2bfloat16(v - __bfloat162float(h));
        size_t base = (size_t)m * 2 * CC;
        g_w2qkv[base + k] = h; g_w2qkv[base + CC + k] = l;
    } else if (idx < NSTEM + NQKV + NOUT) {
        int j = idx - NSTEM - NQKV;
        int m = j / CC, k = j - m * CC;
        float v = out_w[j];
        __nv_bfloat16 h = __float2bfloat16(v);
        __nv_bfloat16 l = __float2bfloat16(v - __bfloat162float(h));
        size_t base = (size_t)m * 2 * CC;
        g_w2out[base + k] = h; g_w2out[base + CC + k] = l;
    }
}

// ================= fused-split HMMA GEMM, templated BM, occ-2 ==============
#define BK 32
#define SP 40

template <int BM>
__device__ __forceinline__ void load_a_chunk(const float* __restrict__ A, int stem,
                                             int row, int K, int cbase, float4* av) {
    constexpr int NF4 = BM / 32;
    if (!stem) {
        const float* p = A + (size_t)row * K + cbase;
#pragma unroll
        for (int j = 0; j < NF4; j++) av[j] = *reinterpret_cast<const float4*>(p + 4 * j);
    } else {
        int t = row & (LL - 1);
#pragma unroll
        for (int j = 0; j < NF4; j++) {
            int col = cbase + 4 * j;
            if (col < CC) {
                av[j] = (t > 0) ? *reinterpret_cast<const float4*>(A + (size_t)(row - 1) * CC + col)
                                : make_float4(0.f, 0.f, 0.f, 0.f);
            } else {
                av[j] = *reinterpret_cast<const float4*>(A + (size_t)row * CC + col - CC);
            }
        }
    }
}

template <int BM>
__global__ void __launch_bounds__(256, 2) gemm_tpl(const float* __restrict__ A,
                                                   const __nv_bfloat16* __restrict__ Bw,
                                                   const float* __restrict__ bias,
                                                   float* __restrict__ C,
                                                   float* __restrict__ pool,
                                                   int M, int N, int K, int stem) {
    constexpr int ATILE = BM * SP;
    constexpr int BTILE = 128 * SP;
    constexpr int NF4 = BM / 32;
    constexpr int TPR = 256 / BM;
    constexpr int MT = BM / 32;

    extern __shared__ __align__(16) __nv_bfloat16 sm[];
    __nv_bfloat16* pAh = sm;
    __nv_bfloat16* pAl = sm + 2 * ATILE;
    __nv_bfloat16* pBh = sm + 4 * ATILE;
    __nv_bfloat16* pBl = sm + 4 * ATILE + 2 * BTILE;

    const int tid = threadIdx.x;
    const int lane = tid & 31;
    const int wid = tid >> 5;
    const int wm = (wid >> 2) * (BM / 2);
    const int wn = (wid & 3) * 32;
    const int m0 = blockIdx.y * BM;
    const int n0 = blockIdx.x * 128;

    float acc[MT][4][4];
#pragma unroll
    for (int i = 0; i < MT; i++)
#pragma unroll
        for (int j = 0; j < 4; j++)
#pragma unroll
            for (int r = 0; r < 4; r++) acc[i][j][r] = 0.0f;

    const int lrowA = tid / TPR;
    const int lcolA = (tid % TPR) * (32 / TPR);
    const int lrowB = tid >> 1;
    const int lhalfB = (tid & 1) * 16;
    const __nv_bfloat16* BgpH = Bw + (size_t)(n0 + lrowB) * (2 * K) + lhalfB;
    const __nv_bfloat16* BgpL = BgpH + K;

    const uint32_t uAh = smem_to_u32(pAh);
    const uint32_t uAl = smem_to_u32(pAl);
    const uint32_t uBh = smem_to_u32(pBh);
    const uint32_t uBl = smem_to_u32(pBl);

    const uint32_t aoffA = (uint32_t)(lrowA * SP + lcolA) * 2;
    const uint32_t boffB = (uint32_t)(lrowB * SP + lhalfB) * 2;

    float4 av[NF4];

#define CONVERT_STS(BUF) do {                                                           \
        uint32_t hb[2 * NF4], lb[2 * NF4];                                              \
        _Pragma("unroll")                                                               \
        for (int j = 0; j < NF4; j++) {                                                 \
            __nv_bfloat162 h01 = __float22bfloat162_rn(make_float2(av[j].x, av[j].y));  \
            __nv_bfloat162 h23 = __float22bfloat162_rn(make_float2(av[j].z, av[j].w));  \
            float2 f01 = __bfloat1622float2(h01);                                       \
            float2 f23 = __bfloat1622float2(h23);                                       \
            __nv_bfloat162 l01 = __float22bfloat162_rn(make_float2(av[j].x - f01.x, av[j].y - f01.y)); \
            __nv_bfloat162 l23 = __float22bfloat162_rn(make_float2(av[j].z - f23.x, av[j].w - f23.y)); \
            hb[2 * j] = *reinterpret_cast<uint32_t*>(&h01);                             \
            hb[2 * j + 1] = *reinterpret_cast<uint32_t*>(&h23);                         \
            lb[2 * j] = *reinterpret_cast<uint32_t*>(&l01);                             \
            lb[2 * j + 1] = *reinterpret_cast<uint32_t*>(&l23);                         \
        }                                                                               \
        _Pragma("unroll")                                                               \
        for (int j = 0; j < NF4 / 2; j++) {                                             \
            STS128A(uAh + (BUF) * (ATILE * 2) + aoffA + j * 16,                         \
                    hb[4 * j], hb[4 * j + 1], hb[4 * j + 2], hb[4 * j + 3]);            \
            STS128A(uAl + (BUF) * (ATILE * 2) + aoffA + j * 16,                         \
                    lb[4 * j], lb[4 * j + 1], lb[4 * j + 2], lb[4 * j + 3]);            \
        }                                                                               \
    } while (0)

#define CP_B(BUF, KO) do {                                                              \
        uint32_t dh = uBh + (BUF) * (BTILE * 2) + boffB;                                \
        uint32_t dl = uBl + (BUF) * (BTILE * 2) + boffB;                                \
        CP_ASYNC16(dh,      BgpH + (KO));                                               \
        CP_ASYNC16(dh + 16, BgpH + (KO) + 8);                                           \
        CP_ASYNC16(dl,      BgpL + (KO));                                               \
        CP_ASYNC16(dl + 16, BgpL + (KO) + 8);                                           \
    } while (0)

    const int NT = K / BK;

    CP_B(0, 0);
    CP_COMMIT();
    load_a_chunk<BM>(A, stem, m0 + lrowA, K, lcolA, av);
    CONVERT_STS(0);
    if (NT > 1) load_a_chunk<BM>(A, stem, m0 + lrowA, K, BK + lcolA, av);
    CP_WAIT0();
    __syncthreads();

    for (int it = 0; it < NT; it++) {
        const int buf = it & 1;
        const bool more = (it + 1) < NT;
        if (more) {
            CP_B(buf ^ 1, (it + 1) * BK);
            CP_COMMIT();
            CONVERT_STS(buf ^ 1);
            if (it + 2 < NT)
                load_a_chunk<BM>(A, stem, m0 + lrowA, K, (it + 2) * BK + lcolA, av);
        }
#pragma unroll
        for (int ks = 0; ks < 2; ks++) {
            uint32_t bhf[4][2], blf[4][2];
            const int quad = lane >> 3;
            const int brr = lane & 7;
#pragma unroll
            for (int p = 0; p < 2; p++) {
                int row = wn + (p * 2 + (quad >> 1)) * 8 + brr;
                int col = ks * 16 + (quad & 1) * 8;
                uint32_t addr = uBh + buf * (BTILE * 2) + (uint32_t)(row * SP + col) * 2;
                asm("ldmatrix.sync.aligned.m8n8.x4.shared.b16 {%0,%1,%2,%3}, [%4];"
                    : "=r"(bhf[p * 2][0]), "=r"(bhf[p * 2][1]),
                      "=r"(bhf[p * 2 + 1][0]), "=r"(bhf[p * 2 + 1][1])
                    : "r"(addr));
                uint32_t addr2 = uBl + buf * (BTILE * 2) + (uint32_t)(row * SP + col) * 2;
                asm("ldmatrix.sync.aligned.m8n8.x4.shared.b16 {%0,%1,%2,%3}, [%4];"
                    : "=r"(blf[p * 2][0]), "=r"(blf[p * 2][1]),
                      "=r"(blf[p * 2 + 1][0]), "=r"(blf[p * 2 + 1][1])
                    : "r"(addr2));
            }
            const int arow = lane & 15;
            const int acol = ks * 16 + ((lane >> 4) << 3);
#define DO_MMA(AC, AF, BF)                                                      \
            asm("mma.sync.aligned.m16n8k16.row.col.f32.bf16.bf16.f32 "           \
                "{%0,%1,%2,%3}, {%4,%5,%6,%7}, {%8,%9}, {%0,%1,%2,%3};"          \
                : "+f"((AC)[0]), "+f"((AC)[1]), "+f"((AC)[2]), "+f"((AC)[3])     \
                : "r"((AF)[0]), "r"((AF)[1]), "r"((AF)[2]), "r"((AF)[3]),        \
                  "r"((BF)[0]), "r"((BF)[1]))
#pragma unroll
            for (int mt = 0; mt < MT; mt++) {
                uint32_t ah[4], al[4];
                uint32_t addr = uAh + buf * (ATILE * 2) +
                                (uint32_t)((wm + mt * 16 + arow) * SP + acol) * 2;
                asm("ldmatrix.sync.aligned.m8n8.x4.shared.b16 {%0,%1,%2,%3}, [%4];"
                    : "=r"(ah[0]), "=r"(ah[1]), "=r"(ah[2]), "=r"(ah[3])
                    : "r"(addr));
                uint32_t addr2 = uAl + buf * (ATILE * 2) +
                                 (uint32_t)((wm + mt * 16 + arow) * SP + acol) * 2;
                asm("ldmatrix.sync.aligned.m8n8.x4.shared.b16 {%0,%1,%2,%3}, [%4];"
                    : "=r"(al[0]), "=r"(al[1]), "=r"(al[2]), "=r"(al[3])
                    : "r"(addr2));
#pragma unroll
                for (int nt = 0; nt < 4; nt++) DO_MMA(acc[mt][nt], ah, bhf[nt]);
#pragma unroll
                for (int nt = 0; nt < 4; nt++) DO_MMA(acc[mt][nt], ah, blf[nt]);
#pragma unroll
                for (int nt = 0; nt < 4; nt++) DO_MMA(acc[mt][nt], al, bhf[nt]);
            }
#undef DO_MMA
        }
        if (more) {
            CP_WAIT0();
            __syncthreads();
        }
    }
#undef CONVERT_STS
#undef CP_B

    // epilogue (+ optional fused mean-pool by 2)
    const int g = lane >> 2;
    const int t = lane & 3;
#pragma unroll
    for (int mt = 0; mt < MT; mt++) {
#pragma unroll
        for (int nt = 0; nt < 4; nt++) {
            int row = m0 + wm + mt * 16 + g;
            int col = n0 + wn + nt * 8 + 2 * t;
            float b0 = 0.f, b1 = 0.f;
            if (bias) { b0 = bias[col]; b1 = bias[col + 1]; }
            float2 v0, v1;
            v0.x = acc[mt][nt][0] + b0; v0.y = acc[mt][nt][1] + b1;
            v1.x = acc[mt][nt][2] + b0; v1.y = acc[mt][nt][3] + b1;
            *reinterpret_cast<float2*>(C + (size_t)row * N + col) = v0;
            *reinterpret_cast<float2*>(C + (size_t)(row + 8) * N + col) = v1;
            if (pool) {
                float p00 = v0.x + __shfl_xor_sync(0xffffffffu, v0.x, 4);
                float p01 = v0.y + __shfl_xor_sync(0xffffffffu, v0.y, 4);
                float p10 = v1.x + __shfl_xor_sync(0xffffffffu, v1.x, 4);
                float p11 = v1.y + __shfl_xor_sync(0xffffffffu, v1.y, 4);
                if ((g & 1) == 0) {
                    float2 q0, q1;
                    q0.x = 0.5f * p00; q0.y = 0.5f * p01;
                    q1.x = 0.5f * p10; q1.y = 0.5f * p11;
                    *reinterpret_cast<float2*>(pool + (size_t)(row >> 1) * N + col) = q0;
                    *reinterpret_cast<float2*>(pool + (size_t)((row + 8) >> 1) * N + col) = q1;
                }
            }
        }
    }
}

// ================= windowed attention: 2 pos/warp, 16 pos/block (R10) =======
__global__ void __launch_bounds__(256) attn_kernel(const float* __restrict__ h,
                                                   const float* __restrict__ qkv,
                                                   const float* __restrict__ width_w,
                                                   const float* __restrict__ width_b,
                                                   float* __restrict__ ov,
                                                   int l) {
    extern __shared__ float smem_attn[];
    float* sk = smem_attn;              // [32][256]
    float* sv = smem_attn + 32 * 256;   // [32][256]

    const int tid = threadIdx.x;
    const int lane = tid & 31;
    const int wid = tid >> 5;
    const int nb = l >> 4;
    const int b = blockIdx.x / nb;
    const int t0 = (blockIdx.x - b * nb) << 4;

    // rows t0-8 .. t0+23 (zero-pad OOB)
    for (int idx = tid; idx < 32 * 64; idx += 256) {
        int row = idx >> 6;
        int c4 = (idx & 63) << 2;
        int kt = t0 - HALFW + row;
        float4 kv = make_float4(0.f, 0.f, 0.f, 0.f);
        float4 vv = kv;
        if (kt >= 0 && kt < l) {
            const float* base = qkv + ((size_t)(b * l + kt)) * (3 * CC);
            kv = *reinterpret_cast<const float4*>(base + CC + c4);
            vv = *reinterpret_cast<const float4*>(base + 2 * CC + c4);
        }
        *reinterpret_cast<float4*>(sk + row * 256 + c4) = kv;
        *reinterpret_cast<float4*>(sv + row * 256 + c4) = vv;
    }
    __syncthreads();

    // warp handles positions p0 = t0+2*wid, p1 = p0+1; window rows 2*wid + [0,18)
    const int p0 = t0 + 2 * wid;
    const float* h0 = h + (size_t)(b * l + p0) * CC;
    const float* h1 = h0 + CC;
    const float* q0r = qkv + (size_t)(b * l + p0) * (3 * CC);
    const float* q1r = q0r + 3 * CC;

    float q0[8], q1[8];
    float ws0 = 0.0f, ws1 = 0.0f;
#pragma unroll
    for (int j = 0; j < 8; j++) {
        int c = lane + 32 * j;
        q0[j] = q0r[c];
        q1[j] = q1r[c];
        float ww = width_w[c];
        ws0 = fmaf(h0[c], ww, ws0);
        ws1 = fmaf(h1[c], ww, ws1);
    }
#pragma unroll
    for (int o = 16; o > 0; o >>= 1) {
        ws0 += __shfl_xor_sync(0xffffffffu, ws0, o);
        ws1 += __shfl_xor_sync(0xffffffffu, ws1, o);
    }
    float wb = width_b[0];
    float width0 = sigmoidf_(ws0 + wb) * (float)HALFW + 0.5f;
    float width1 = sigmoidf_(ws1 + wb) * (float)HALFW + 0.5f;

    float s0[KW], s1[KW];
#pragma unroll
    for (int r = 0; r < 18; r++) {
        const float* krow = sk + (2 * wid + r) * 256;
        float kv[8];
#pragma unroll
        for (int j = 0; j < 8; j++) kv[j] = krow[lane + 32 * j];
        if (r < KW) {
            float p = 0.0f;
#pragma unroll
            for (int j = 0; j < 8; j++) p = fmaf(q0[j], kv[j], p);
            s0[r] = p;
        }
        if (r > 0) {
            float p = 0.0f;
#pragma unroll
            for (int j = 0; j < 8; j++) p = fmaf(q1[j], kv[j], p);
            s1[r - 1] = p;
        }
    }
#pragma unroll
    for (int w = 0; w < KW; w++) {
        float a = s0[w], c = s1[w];
#pragma unroll
        for (int o = 16; o > 0; o >>= 1) {
            a += __shfl_xor_sync(0xffffffffu, a, o);
            c += __shfl_xor_sync(0xffffffffu, c, o);
        }
        float rel = fabsf((float)(w - HALFW));
        s0[w] = a * 0.0625f - (1.0f - sigmoidf_((width0 - rel) * 5.0f)) * 10000.0f;
        s1[w] = c * 0.0625f - (1.0f - sigmoidf_((width1 - rel) * 5.0f)) * 10000.0f;
    }

    float mx0 = s0[0], mx1 = s1[0];
#pragma unroll
    for (int w = 1; w < KW; w++) { mx0 = fmaxf(mx0, s0[w]); mx1 = fmaxf(mx1, s1[w]); }
    float d0 = 0.0f, d1 = 0.0f;
#pragma unroll
    for (int w = 0; w < KW; w++) {
        s0[w] = __expf(s0[w] - mx0); d0 += s0[w];
        s1[w] = __expf(s1[w] - mx1); d1 += s1[w];
    }
    float i0 = 1.0f / d0, i1 = 1.0f / d1;
#pragma unroll
    for (int w = 0; w < KW; w++) { s0[w] *= i0; s1[w] *= i1; }

    float o0[8], o1[8];
    const float* vs0 = sv + (2 * wid + HALFW) * 256;
#pragma unroll
    for (int j = 0; j < 8; j++) {
        o0[j] = vs0[lane + 32 * j];
        o1[j] = vs0[256 + lane + 32 * j];
    }
#pragma unroll
    for (int r = 0; r < 18; r++) {
        const float* vrow = sv + (2 * wid + r) * 256;
        float vv[8];
#pragma unroll
        for (int j = 0; j < 8; j++) vv[j] = vrow[lane + 32 * j];
        if (r < KW) {
            float a = s0[r];
#pragma unroll
            for (int j = 0; j < 8; j++) o0[j] = fmaf(a, vv[j], o0[j]);
        }
        if (r > 0) {
            float a = s1[r - 1];
#pragma unroll
            for (int j = 0; j < 8; j++) o1[j] = fmaf(a, vv[j], o1[j]);
        }
    }
    float* or0 = ov + (size_t)(b * l + p0) * CC;
#pragma unroll
    for (int j = 0; j < 8; j++) {
        or0[lane + 32 * j] = o0[j];
        or0[CC + lane + 32 * j] = o1[j];
    }
}

// ================= global attention logits (float4) =================
__global__ void logits_kernel(const float* __restrict__ query) {
    int gwarp = (blockIdx.x * blockDim.x + threadIdx.x) >> 5;
    int lane = threadIdx.x & 31;
    if (gwarp >= BB * LL) return;
    int b = gwarp / LL;
    int t = gwarp - b * LL;
    const float* r0 = g_lev0 + ((size_t)(b * LL + t)) * CC;
    const float* r1 = g_lev1 + ((size_t)(b * (LL / 2) + (t >> 1))) * CC;
    const float* r2 = g_lev2 + ((size_t)(b * (LL / 4) + (t >> 2))) * CC;
    const float* r3 = g_lev3 + ((size_t)(b * (LL / 8) + (t >> 3))) * CC;
    float s = 0.0f;
#pragma unroll
    for (int j = 0; j < 2; j++) {
        int c = (lane + 32 * j) * 4;
        float4 a0 = *reinterpret_cast<const float4*>(r0 + c);
        float4 a1 = *reinterpret_cast<const float4*>(r1 + c);
        float4 a2 = *reinterpret_cast<const float4*>(r2 + c);
        float4 a3 = *reinterpret_cast<const float4*>(r3 + c);
        float4 q0 = *reinterpret_cast<const float4*>(query + c);
        float4 q1 = *reinterpret_cast<const float4*>(query + CC + c);
        float4 q2 = *reinterpret_cast<const float4*>(query + 2 * CC + c);
        float4 q3 = *reinterpret_cast<const float4*>(query + 3 * CC + c);
        s = fmaf(a0.x, q0.x, s); s = fmaf(a0.y, q0.y, s); s = fmaf(a0.z, q0.z, s); s = fmaf(a0.w, q0.w, s);
        s = fmaf(a1.x, q1.x, s); s = fmaf(a1.y, q1.y, s); s = fmaf(a1.z, q1.z, s); s = fmaf(a1.w, q1.w, s);
        s = fmaf(a2.x, q2.x, s); s = fmaf(a2.y, q2.y, s); s = fmaf(a2.z, q2.z, s); s = fmaf(a2.w, q2.w, s);
        s = fmaf(a3.x, q3.x, s); s = fmaf(a3.y, q3.y, s); s = fmaf(a3.z, q3.z, s); s = fmaf(a3.w, q3.w, s);
    }
#pragma unroll
    for (int o = 16; o > 0; o >>= 1) s += __shfl_xor_sync(0xffffffffu, s, o);
    if (lane == 0) g_logits[gwarp] = s;
}

// ================= softmax over L per batch (1024 thr) =================
__global__ void softmax_kernel() {
    __shared__ float sl[LL];
    __shared__ float red[1024];
    int b = blockIdx.x;
    int tid = threadIdx.x;
    const float* lg = g_logits + (size_t)b * LL;
    float mx = -1e30f;
    for (int t = tid; t < LL; t += 1024) { float v = lg[t]; sl[t] = v; mx = fmaxf(mx, v); }
    red[tid] = mx; __syncthreads();
    for (int o = 512; o > 0; o >>= 1) { if (tid < o) red[tid] = fmaxf(red[tid], red[tid + o]); __syncthreads(); }
    mx = red[0]; __syncthreads();
    float sum = 0.0f;
    for (int t = tid; t < LL; t += 1024) { float e = expf(sl[t] - mx); sl[t] = e; sum += e; }
    red[tid] = sum; __syncthreads();
    for (int o = 512; o > 0; o >>= 1) { if (tid < o) red[tid] += red[tid + o]; __syncthreads(); }
    float inv = 1.0f / red[0];
    for (int t = tid; t < LL; t += 1024) g_gattn[(size_t)b * LL + t] = sl[t] * inv;
}

// ================= ctx partial reduction =================
__global__ void ctx_part_kernel() {
    int i = blockIdx.x;
    int b = blockIdx.y;
    int ch = blockIdx.z;
    int c = threadIdx.x;
    const float* lev = (i == 0) ? g_lev0 : (i == 1) ? g_lev1 : (i == 2) ? g_lev2 : g_lev3;
    int li = LL >> i;
    const float* ga = g_gattn + (size_t)b * LL;
    const float* base = lev + (size_t)b * li * CC + c;
    const int span = LL / CTX_CHUNKS;
    const int t0 = ch * span;
    float a0 = 0.f, a1 = 0.f, a2 = 0.f, a3 = 0.f;
    for (int t = t0; t < t0 + span; t += 4) {
        a0 = fmaf(ga[t + 0], base[(size_t)((t + 0) >> i) * CC], a0);
        a1 = fmaf(ga[t + 1], base[(size_t)((t + 1) >> i) * CC], a1);
        a2 = fmaf(ga[t + 2], base[(size_t)((t + 2) >> i) * CC], a2);
        a3 = fmaf(ga[t + 3], base[(size_t)((t + 3) >> i) * CC], a3);
    }
    g_ctxpart[(((size_t)i * BB + b) * CTX_CHUNKS + ch) * CC + c] = (a0 + a1) + (a2 + a3);
}

// ================= FiLM (folds ctx reduction) =================
__global__ void film_kernel(const float* __restrict__ film_w, const float* __restrict__ film_b) {
    __shared__ float sc[NLEV * CC];
    int b = blockIdx.x;
    int o = threadIdx.x;
    for (int d = o; d < NLEV * CC; d += 512) {
        int i = d >> 8, c = d & 255;
        const float* p = g_ctxpart + (((size_t)i * BB + b) * CTX_CHUNKS) * CC + c;
        float s = 0.0f;
#pragma unroll
        for (int ch = 0; ch < CTX_CHUNKS; ch++) s += p[(size_t)ch * CC];
        sc[d] = s;
    }
    __syncthreads();
    const float* wr = film_w + (size_t)o * (NLEV * CC);
    float acc = 0.0f;
#pragma unroll 8
    for (int d = 0; d < NLEV * CC; d++) acc = fmaf(sc[d], wr[d], acc);
    g_film[(size_t)b * (2 * CC) + o] = acc + film_b[o];
}

// ================= final (float4) =================
__global__ void final_kernel(float* __restrict__ out) {
    int idx = blockIdx.x * blockDim.x + threadIdx.x;
    if (idx >= BB * LL * CC / 4) return;
    int c4 = (idx << 2) & (CC - 1);
    int b = (idx << 2) / (LL * CC);
    float4 lv = *reinterpret_cast<const float4*>(&g_lev0[(size_t)idx << 2]);
    const float* fb = g_film + (size_t)b * (2 * CC);
    float4 sc = *reinterpret_cast<const float4*>(fb + c4);
    float4 bi = *reinterpret_cast<const float4*>(fb + CC + c4);
    float4 r;
    r.x = fmaf(lv.x, 1.0f + sc.x, bi.x);
    r.y = fmaf(lv.y, 1.0f + sc.y, bi.y);
    r.z = fmaf(lv.z, 1.0f + sc.z, bi.z);
    r.w = fmaf(lv.w, 1.0f + sc.w, bi.w);
    *reinterpret_cast<float4*>(out + ((size_t)idx << 2)) = r;
}

// ================= launch =================
static void launch_gemm(const float* A, const __nv_bfloat16* Bw, const float* bias,
                        float* C, float* pool, int M, int N, int K, int stem) {
    int ctas128 = (N / 128) * (M / 128);
    if (ctas128 >= 148) {
        int smem = (4 * 128 + 4 * 128) * SP * 2;
        cudaFuncSetAttribute(gemm_tpl<128>, cudaFuncAttributeMaxDynamicSharedMemorySize, smem);
        dim3 grid(N / 128, M / 128);
        gemm_tpl<128><<<grid, 256, smem>>>(A, Bw, bias, C, pool, M, N, K, stem);
    } else {
        int smem = (4 * 64 + 4 * 128) * SP * 2;
        cudaFuncSetAttribute(gemm_tpl<64>, cudaFuncAttributeMaxDynamicSharedMemorySize, smem);
        dim3 grid(N / 128, M / 64);
        gemm_tpl<64><<<grid, 256, smem>>>(A, Bw, bias, C, pool, M, N, K, stem);
    }
}

extern "C" void kernel_launch(void* const* d_in, const int* in_sizes, int n_in,
                              void* d_out, int out_size) {
    const float* x       = (const float*)d_in[0];
    const float* stem_w  = (const float*)d_in[1];
    const float* stem_b  = (const float*)d_in[2];
    const float* qkv_w   = (const float*)d_in[3];
    const float* width_w = (const float*)d_in[4];
    const float* width_b = (const float*)d_in[5];
    const float* out_w   = (const float*)d_in[6];
    const float* query   = (const float*)d_in[7];
    const float* film_w  = (const float*)d_in[8];
    const float* film_b  = (const float*)d_in[9];
    float* out = (float*)d_out;

    cudaFuncSetAttribute(attn_kernel, cudaFuncAttributeMaxDynamicSharedMemorySize, 65536);

    float *p_h, *p_qkv, *p_ov, *p_lev[4];
    __nv_bfloat16 *p_w2stem, *p_w2qkv, *p_w2out;
    cudaGetSymbolAddress((void**)&p_h, g_h);
    cudaGetSymbolAddress((void**)&p_qkv, g_qkv);
    cudaGetSymbolAddress((void**)&p_ov, g_ov);
    cudaGetSymbolAddress((void**)&p_lev[0], g_lev0);
    cudaGetSymbolAddress((void**)&p_lev[1], g_lev1);
    cudaGetSymbolAddress((void**)&p_lev[2], g_lev2);
    cudaGetSymbolAddress((void**)&p_lev[3], g_lev3);
    cudaGetSymbolAddress((void**)&p_w2stem, g_w2stem);
    cudaGetSymbolAddress((void**)&p_w2qkv, g_w2qkv);
    cudaGetSymbolAddress((void**)&p_w2out, g_w2out);

    const int M = BB * LL;

    {
        int total = CC * 512 + 3 * CC * CC + CC * CC;
        split_all_kernel<<<(total + 255) / 256, 256>>>(stem_w, qkv_w, out_w);
    }

    // stem
    launch_gemm(x, p_w2stem, stem_b, p_h, nullptr, M, CC, 512, 1);

    // levels (downsample fused into out-proj epilogue)
    for (int i = 0; i < NLEV; i++) {
        int l = LL >> i;
        int Mi = BB * l;
        launch_gemm(p_h, p_w2qkv, nullptr, p_qkv, nullptr, Mi, 3 * CC, CC, 0);
        attn_kernel<<<Mi / 16, 256, 65536>>>(p_h, p_qkv, width_w, width_b, p_ov, l);
        float* pool = (i < NLEV - 1) ? p_h : nullptr;
        launch_gemm(p_ov, p_w2out, nullptr, p_lev[i], pool, Mi, CC, CC, 0);
    }

    // global attention + FiLM
    logits_kernel<<<(BB * LL) / 8, 256>>>(query);
    softmax_kernel<<<BB, 1024>>>();
    ctx_part_kernel<<<dim3(NLEV, BB, CTX_CHUNKS), CC>>>();
    film_kernel<<<BB, 2 * CC>>>(film_w, film_b);
    final_kernel<<<(BB * LL * CC / 4 + 255) / 256, 256>>>(out);
}